// round 17
// baseline (speedup 1.0000x reference)
#include <cuda_runtime.h>
#include <cuda_bf16.h>
#include <math.h>
#include <stdint.h>

#define BATCH 4
#define CH    256
#define NSP   4096
#define DQK   32

// ---------------- scratch (__device__ globals: no runtime allocation) -------
__device__ __align__(256) unsigned short g_Qh16[BATCH*NSP*DQK]; // [b][n][d] bf16 hi (pre-scaled)
__device__ __align__(256) unsigned short g_Ql16[BATCH*NSP*DQK]; // [b][n][d] bf16 lo
__device__ __align__(256) unsigned short g_Kh16[BATCH*NSP*DQK]; // [b][n][d] bf16 hi
__device__ __align__(256) unsigned short g_Kl16[BATCH*NSP*DQK]; // [b][n][d] bf16 lo
__device__ __align__(256) unsigned short g_Vb[BATCH*CH*NSP];    // [b][e][n] bf16
__device__ __align__(256) float g_O[BATCH*NSP*CH];              // [b][n][e]
__device__ __align__(256) float g_G0[CH*CH];
__device__ __align__(256) float g_GA[CH*CH];
__device__ __align__(256) float g_GB[CH*CH];
__device__ float g_tr[16];
__device__ float g_sigma[4];   // [0]=sigma_q [1]=sigma_k [2]=sigma_v

// ---------------- helpers ----------------------------------------------------
// pack {lo(addr even), hi(addr odd)} into bf16x2 (first src -> upper half)
__device__ __forceinline__ uint32_t pkbf16(float lo, float hi){
    uint32_t u;
    asm("cvt.rn.bf16x2.f32 %0, %1, %2;" : "=r"(u) : "f"(hi), "f"(lo));
    return u;
}
// D += A(16x16,row,bf16) * B(16x8,col,bf16)
__device__ __forceinline__ void mma_bf16(float* c, const uint32_t* a,
                                         uint32_t b0, uint32_t b1){
    asm volatile(
        "mma.sync.aligned.m16n8k16.row.col.f32.bf16.bf16.f32 "
        "{%0,%1,%2,%3}, {%4,%5,%6,%7}, {%8,%9}, {%0,%1,%2,%3};\n"
        : "+f"(c[0]), "+f"(c[1]), "+f"(c[2]), "+f"(c[3])
        : "r"(a[0]), "r"(a[1]), "r"(a[2]), "r"(a[3]), "r"(b0), "r"(b1));
}

// ---------------- cp.async helpers ------------------------------------------
__device__ __forceinline__ void cpa16(const void* dst, const void* src){
    uint32_t d = (uint32_t)__cvta_generic_to_shared(dst);
    asm volatile("cp.async.cg.shared.global [%0], [%1], 16;"
                 :: "r"(d), "l"(src) : "memory");
}
#define CP_COMMIT() asm volatile("cp.async.commit_group;" ::: "memory")
#define CP_WAIT(n)  asm volatile("cp.async.wait_group %0;" :: "n"(n) : "memory")

// ---------------- init ------------------------------------------------------
__global__ void init_kernel(){
    if (threadIdx.x < 16) g_tr[threadIdx.x] = 0.0f;
}

// ---------------- sigma for wq / wk (32x256) --------------------------------
__global__ void sigma_qk_kernel(const float* __restrict__ wq,
                                const float* __restrict__ wk){
    const float* W = (blockIdx.x == 0) ? wq : wk;
    __shared__ float Ws[32][257];
    __shared__ float Ao[32][33];
    __shared__ float Aa[32][33];
    __shared__ float Ab[32][33];
    __shared__ float vsh[32];
    __shared__ float tinv;
    int tid = threadIdx.x;

    for (int m = 0; m < 8; m++){
        int lin = m*1024 + tid;
        Ws[lin >> 8][lin & 255] = W[lin];
    }
    __syncthreads();

    int i = tid >> 5, j = tid & 31;
    float a = 0.f;
    #pragma unroll 8
    for (int c = 0; c < 256; c++) a += Ws[i][c] * Ws[j][c];
    Ao[i][j] = a;
    Aa[i][j] = a;
    __syncthreads();

    for (int s = 0; s < 5; s++){
        float (*cur)[33] = (s & 1) ? Ab : Aa;
        float (*nxt)[33] = (s & 1) ? Aa : Ab;
        if (tid == 0){
            float t = 0.f;
            for (int k2 = 0; k2 < 32; k2++) t += cur[k2][k2];
            tinv = 1.0f / t;
        }
        __syncthreads();
        float acc = 0.f;
        #pragma unroll
        for (int k2 = 0; k2 < 32; k2++) acc += cur[i][k2] * cur[j][k2];
        float ti = tinv;
        nxt[i][j] = acc * ti * ti;
        __syncthreads();
    }

    if (tid < 32){
        vsh[tid] = 1.0f + 0.05f * (float)tid;
        __syncwarp();
        for (int it = 0; it < 40; it++){
            float w = 0.f;
            #pragma unroll
            for (int k2 = 0; k2 < 32; k2++) w += Ab[tid][k2] * vsh[k2];
            float ss = w * w;
            #pragma unroll
            for (int off = 16; off; off >>= 1) ss += __shfl_xor_sync(0xffffffffu, ss, off);
            float sc = rsqrtf(ss);
            __syncwarp();
            vsh[tid] = w * sc;
            __syncwarp();
        }
        float w = 0.f;
        #pragma unroll
        for (int k2 = 0; k2 < 32; k2++) w += Ao[tid][k2] * vsh[k2];
        float num = vsh[tid] * w, den = vsh[tid] * vsh[tid];
        #pragma unroll
        for (int off = 16; off; off >>= 1){
            num += __shfl_xor_sync(0xffffffffu, num, off);
            den += __shfl_xor_sync(0xffffffffu, den, off);
        }
        if (tid == 0) g_sigma[blockIdx.x] = sqrtf(num / den);
    }
}

// ---------------- Gram of wv: G0 = wv wv^T (256x256) ------------------------
__global__ void gram_v_kernel(const float* __restrict__ wv){
    __shared__ float as[32][33], bs[32][33];
    int tid = threadIdx.x;
    int i0 = blockIdx.y * 32, j0 = blockIdx.x * 32;
    int li = tid >> 5, lj = tid & 31;
    float acc = 0.f;
    for (int c0 = 0; c0 < 256; c0 += 32){
        as[li][lj] = wv[(i0 + li)*256 + c0 + lj];
        bs[li][lj] = wv[(j0 + li)*256 + c0 + lj];
        __syncthreads();
        #pragma unroll
        for (int cc = 0; cc < 32; cc++) acc += as[li][cc] * bs[lj][cc];
        __syncthreads();
    }
    g_G0[(i0 + li)*256 + j0 + lj] = acc;
    if (i0 + li == j0 + lj) atomicAdd(&g_tr[0], acc);
}

// ---------------- one trace-normalized squaring of a 256x256 PSD matrix -----
__device__ __forceinline__ float* gbuf(int s){
    return (s == 0) ? g_G0 : ((s == 1) ? g_GA : g_GB);
}
__global__ void sq_v_kernel(int ssel, int dsel, int step){
    const float* src = gbuf(ssel);
    float* dst = gbuf(dsel);
    __shared__ float as[32][33], bs[32][33];
    int tid = threadIdx.x;
    int i0 = blockIdx.y * 32, j0 = blockIdx.x * 32;
    int li = tid >> 5, lj = tid & 31;
    float inv = 1.0f / g_tr[step];
    float acc = 0.f;
    for (int k0 = 0; k0 < 256; k0 += 32){
        as[li][lj] = src[(i0 + li)*256 + k0 + lj];
        bs[li][lj] = src[(j0 + li)*256 + k0 + lj];
        __syncthreads();
        #pragma unroll
        for (int kk = 0; kk < 32; kk++) acc += as[li][kk] * bs[lj][kk];
        __syncthreads();
    }
    acc = acc * inv * inv;
    dst[(i0 + li)*256 + j0 + lj] = acc;
    if (i0 + li == j0 + lj) atomicAdd(&g_tr[step + 1], acc);
}

// ---------------- power + Rayleigh for sigma_v ------------------------------
__global__ void power_v_kernel(){
    __shared__ float vsh[256], vnew[256];
    __shared__ float rss[8], rnum[8], rden[8];
    __shared__ float nscale;
    int tid = threadIdx.x;                // 1024 threads
    int lane = tid & 31, wrp = tid >> 5;
    if (tid < 256) vsh[tid] = 1.0f + 0.013f * (float)tid;
    __syncthreads();

    for (int it = 0; it < 9; it++){
        const float* Mat = (it < 8) ? g_GB : g_G0;
        float part[8] = {0,0,0,0,0,0,0,0};
        #pragma unroll
        for (int m = 0; m < 8; m++){
            int k2 = lane + 32*m;
            float vk = vsh[k2];
            #pragma unroll
            for (int i = 0; i < 8; i++)
                part[i] += Mat[(wrp*8 + i)*256 + k2] * vk;
        }
        #pragma unroll
        for (int i = 0; i < 8; i++){
            float r = part[i];
            #pragma unroll
            for (int off = 16; off; off >>= 1) r += __shfl_down_sync(0xffffffffu, r, off);
            if (lane == 0) vnew[wrp*8 + i] = r;
        }
        __syncthreads();
        if (it < 8){
            if (tid < 256){
                float s2 = vnew[tid] * vnew[tid];
                #pragma unroll
                for (int off = 16; off; off >>= 1) s2 += __shfl_down_sync(0xffffffffu, s2, off);
                if ((tid & 31) == 0) rss[tid >> 5] = s2;
            }
            __syncthreads();
            if (tid == 0){
                float s2 = 0.f;
                for (int u = 0; u < 8; u++) s2 += rss[u];
                nscale = rsqrtf(s2);
            }
            __syncthreads();
            if (tid < 256) vsh[tid] = vnew[tid] * nscale;
            __syncthreads();
        } else {
            if (tid < 256){
                float nv = vsh[tid] * vnew[tid];
                float dv = vsh[tid] * vsh[tid];
                #pragma unroll
                for (int off = 16; off; off >>= 1){
                    nv += __shfl_down_sync(0xffffffffu, nv, off);
                    dv += __shfl_down_sync(0xffffffffu, dv, off);
                }
                if ((tid & 31) == 0){ rnum[tid >> 5] = nv; rden[tid >> 5] = dv; }
            }
            __syncthreads();
            if (tid == 0){
                float n = 0.f, d2 = 0.f;
                for (int u = 0; u < 8; u++){ n += rnum[u]; d2 += rden[u]; }
                g_sigma[2] = sqrtf(n / d2);
            }
        }
    }
}

// ---------------- merged projections ----------------------------------------
// z = 0: Q -> g_Qh16/g_Ql16 [b][n][d] bf16 split, PRE-SCALED by lscale
// z = 1: K -> g_Kh16/g_Kl16 [b][n][d] bf16 split
// z = 2..5: V -> g_Vb [b][e][n] bf16, e0 = (z-2)*64
__global__ void proj_all_kernel(const float* __restrict__ x,
                                const float* __restrict__ wq,
                                const float* __restrict__ wk,
                                const float* __restrict__ wv){
    int z = blockIdx.z;
    int b = blockIdx.y, n0 = blockIdx.x * 64;
    int tid = threadIdx.x;
    const float* xb = x + (size_t)b * CH * NSP;

    if (z < 2){
        const float* W = (z == 0) ? wq : wk;
        unsigned short* dhi = ((z == 0) ? g_Qh16 : g_Kh16) + (size_t)b*NSP*DQK;
        unsigned short* dlo = ((z == 0) ? g_Ql16 : g_Kl16) + (size_t)b*NSP*DQK;
        float lsc = (z == 0)
            ? 1.0f / (g_sigma[0] * g_sigma[1] * sqrtf((float)DQK)) : 1.0f;
        __shared__ float ws[32][33], xs[32][65];
        int d = tid & 31, rg = tid >> 5;
        float acc[8] = {0,0,0,0,0,0,0,0};
        for (int c0 = 0; c0 < 256; c0 += 32){
            #pragma unroll
            for (int m = 0; m < 4; m++){
                int lin = m*256 + tid;
                ws[lin >> 5][lin & 31] = W[(lin >> 5)*256 + c0 + (lin & 31)];
            }
            #pragma unroll
            for (int m = 0; m < 8; m++){
                int lin = m*256 + tid;
                int c = lin >> 6, nn = lin & 63;
                xs[c][nn] = xb[(c0 + c)*NSP + n0 + nn];
            }
            __syncthreads();
            #pragma unroll
            for (int cc = 0; cc < 32; cc++){
                float wv_ = ws[d][cc];
                #pragma unroll
                for (int i = 0; i < 8; i++) acc[i] += wv_ * xs[cc][rg*8 + i];
            }
            __syncthreads();
        }
        #pragma unroll
        for (int i = 0; i < 8; i++){
            float v = acc[i] * lsc;
            __nv_bfloat16 h = __float2bfloat16(v);
            float hf = __bfloat162float(h);
            __nv_bfloat16 l = __float2bfloat16(v - hf);
            size_t idx = (size_t)(n0 + rg*8 + i)*DQK + d;
            dhi[idx] = reinterpret_cast<unsigned short&>(h);
            dlo[idx] = reinterpret_cast<unsigned short&>(l);
        }
    } else {
        int e0 = (z - 2) * 64;
        __shared__ float ws[64][33], xs[32][65];
        int ex = tid & 15, ny = tid >> 4;
        float acc[4][4] = {};
        for (int c0 = 0; c0 < 256; c0 += 32){
            #pragma unroll
            for (int m = 0; m < 8; m++){
                int lin = m*256 + tid;
                ws[lin >> 5][lin & 31] = wv[(e0 + (lin >> 5))*256 + c0 + (lin & 31)];
            }
            #pragma unroll
            for (int m = 0; m < 8; m++){
                int lin = m*256 + tid;
                int c = lin >> 6, nn = lin & 63;
                xs[c][nn] = xb[(c0 + c)*NSP + n0 + nn];
            }
            __syncthreads();
            #pragma unroll
            for (int cc = 0; cc < 32; cc++){
                float er[4], xr[4];
                #pragma unroll
                for (int jc = 0; jc < 4; jc++) er[jc] = ws[ex*4 + jc][cc];
                #pragma unroll
                for (int i = 0; i < 4; i++) xr[i] = xs[cc][ny*4 + i];
                #pragma unroll
                for (int i = 0; i < 4; i++)
                    #pragma unroll
                    for (int jc = 0; jc < 4; jc++)
                        acc[i][jc] += xr[i] * er[jc];
            }
            __syncthreads();
        }
        #pragma unroll
        for (int jc = 0; jc < 4; jc++){
            uint32_t u0 = pkbf16(acc[0][jc], acc[1][jc]);
            uint32_t u1 = pkbf16(acc[2][jc], acc[3][jc]);
            size_t h = (size_t)b*CH*NSP + (size_t)(e0 + ex*4 + jc)*NSP + n0 + ny*4;
            *(uint2*)&g_Vb[h] = make_uint2(u0, u1);
        }
    }
}

// ---------------- flash attention (e-split 2, all-bf16 mma, reg softmax) ----
// smem (u32 offsets):
//   Qh @0     [64 q][20]   (1280)   bf16x2 d-pairs, hi
//   Ql @1280  [64 q][20]   (1280)   lo
//   Kh @2560  [64 k][20]   (1280)
//   Kl @3840  [64 k][20]   (1280)
//   Vu @5120  [128 e][36]  (4608)   bf16x2 k-pairs
//   Pb @9728  [64 q][36]   (2304)   bf16x2 k-pairs (post-softmax)
//   pmax @12032 [64][8] f32 (512), psum @12544 (512)
//   mrow @13056 (64), lrow @13120 (64) -> 13184 u32 = 52736 B
#define FLASH_SMEM 52736

__global__ void __launch_bounds__(256, 4)
flash_kernel(float* __restrict__ Og){
    extern __shared__ uint32_t smu[];
    uint32_t* Qh = smu;
    uint32_t* Ql = smu + 1280;
    uint32_t* Kh = smu + 2560;
    uint32_t* Kl = smu + 3840;
    uint32_t* Vu = smu + 5120;
    uint32_t* Pbu = smu + 9728;
    float* pmax = (float*)(smu + 12032);
    float* psum = (float*)(smu + 12544);
    float* mrow = (float*)(smu + 13056);
    float* lrow = (float*)(smu + 13120);

    int tid = threadIdx.x;
    int i0 = blockIdx.x * 64, eh = blockIdx.y, b = blockIdx.z;
    int w = tid >> 5, lane = tid & 31;
    int gid = lane >> 2, tig = lane & 3;

    const unsigned short* gQh = g_Qh16 + (size_t)b*NSP*DQK;
    const unsigned short* gQl = g_Ql16 + (size_t)b*NSP*DQK;
    const unsigned short* gKh = g_Kh16 + (size_t)b*NSP*DQK;
    const unsigned short* gKl = g_Kl16 + (size_t)b*NSP*DQK;
    const unsigned short* gV  = g_Vb + (size_t)b*CH*NSP + (size_t)(eh*128)*NSP;

    // stage Q (once): rows [64][16 u32] -> [64][20]
    {
        int r = tid >> 2, q4 = tid & 3;
        *(uint4*)(Qh + r*20 + q4*4) =
            *(const uint4*)(gQh + (size_t)(i0 + r)*DQK + q4*8);
        *(uint4*)(Ql + r*20 + q4*4) =
            *(const uint4*)(gQl + (size_t)(i0 + r)*DQK + q4*8);
    }
    if (tid < 64){ mrow[tid] = -INFINITY; lrow[tid] = 0.f; }

    float c[4][2][4];
    #pragma unroll
    for (int mt = 0; mt < 4; mt++)
        #pragma unroll
        for (int nt = 0; nt < 2; nt++)
            #pragma unroll
            for (int r = 0; r < 4; r++) c[mt][nt][r] = 0.f;
    __syncthreads();   // Q staged, rows init

    for (int jt = 0; jt < 64; jt++){
        int j0 = jt * 64;

        // group 1: K tile (hi+lo)
        {
            int r = tid >> 2, q4 = tid & 3;
            cpa16(Kh + r*20 + q4*4, gKh + (size_t)(j0 + r)*DQK + q4*8);
            cpa16(Kl + r*20 + q4*4, gKl + (size_t)(j0 + r)*DQK + q4*8);
        }
        CP_COMMIT();
        // group 2: V half-tile [128 e][64 k] bf16
        #pragma unroll
        for (int i = 0; i < 4; i++){
            int f = i*256 + tid;
            int e = f >> 3, u = f & 7;
            cpa16((unsigned short*)Vu + e*72 + u*8,
                  gV + (size_t)e*NSP + j0 + u*8);
        }
        CP_COMMIT();

        CP_WAIT(1);          // K ready
        __syncthreads();     // [B1]

        // ---- S = Q K^T (bf16 3-term) in registers; this warp: keys 8w..8w+7
        float cs[4][4];
        #pragma unroll
        for (int mt = 0; mt < 4; mt++)
            #pragma unroll
            for (int r = 0; r < 4; r++) cs[mt][r] = 0.f;
        #pragma unroll
        for (int kd = 0; kd < 2; kd++){
            int kbr = (8*w + gid)*20 + kd*8 + tig;
            uint32_t bh0 = Kh[kbr], bh1 = Kh[kbr + 4];
            uint32_t bl0 = Kl[kbr], bl1 = Kl[kbr + 4];
            #pragma unroll
            for (int mt = 0; mt < 4; mt++){
                int r0 = (16*mt + gid)*20 + kd*8 + tig;
                int r1 = r0 + 8*20;
                uint32_t ah[4] = {Qh[r0], Qh[r1], Qh[r0 + 4], Qh[r1 + 4]};
                uint32_t al[4] = {Ql[r0], Ql[r1], Ql[r0 + 4], Ql[r1 + 4]};
                mma_bf16(cs[mt], ah, bh0, bh1);
                mma_bf16(cs[mt], al, bh0, bh1);
                mma_bf16(cs[mt], ah, bl0, bl1);
            }
        }

        // ---- partial row-max -> pmax[row][w]
        #pragma unroll
        for (int mt = 0; mt < 4; mt++){
            float ma = fmaxf(cs[mt][0], cs[mt][1]);
            float mb = fmaxf(cs[mt][2], cs[mt][3]);
            ma = fmaxf(ma, __shfl_xor_sync(0xffffffffu, ma, 1));
            ma = fmaxf(ma, __shfl_xor_sync(0xffffffffu, ma, 2));
            mb = fmaxf(mb, __shfl_xor_sync(0xffffffffu, mb, 1));
            mb = fmaxf(mb, __shfl_xor_sync(0xffffffffu, mb, 2));
            if (tig == 0){
                pmax[(16*mt + gid)*8 + w]     = ma;
                pmax[(16*mt + gid + 8)*8 + w] = mb;
            }
        }
        __syncthreads();     // [B2] pmax complete

        // ---- per-thread softmax: exp in regs, write bf16 Pb + psum
        float alA[4], alB[4];
        #pragma unroll
        for (int mt = 0; mt < 4; mt++){
            int ra = 16*mt + gid;
            int rb = ra + 8;
            float4 pa0 = *(const float4*)&pmax[ra*8];
            float4 pa1 = *(const float4*)&pmax[ra*8 + 4];
            float4 pb0 = *(const float4*)&pmax[rb*8];
            float4 pb1 = *(const float4*)&pmax[rb*8 + 4];
            float mxa = fmaxf(fmaxf(fmaxf(pa0.x, pa0.y), fmaxf(pa0.z, pa0.w)),
                              fmaxf(fmaxf(pa1.x, pa1.y), fmaxf(pa1.z, pa1.w)));
            float mxb = fmaxf(fmaxf(fmaxf(pb0.x, pb0.y), fmaxf(pb0.z, pb0.w)),
                              fmaxf(fmaxf(pb1.x, pb1.y), fmaxf(pb1.z, pb1.w)));
            float mza = fmaxf(mxa, mrow[ra]);
            float mzb = fmaxf(mxb, mrow[rb]);
            alA[mt] = __expf(mrow[ra] - mza);
            alB[mt] = __expf(mrow[rb] - mzb);
            float e0 = __expf(cs[mt][0] - mza);
            float e1 = __expf(cs[mt][1] - mza);
            float e2 = __expf(cs[mt][2] - mzb);
            float e3 = __expf(cs[mt][3] - mzb);
            Pbu[ra*36 + 4*w + tig] = pkbf16(e0, e1);
            Pbu[rb*36 + 4*w + tig] = pkbf16(e2, e3);
            float sa = e0 + e1, sb = e2 + e3;
            sa += __shfl_xor_sync(0xffffffffu, sa, 1);
            sa += __shfl_xor_sync(0xffffffffu, sa, 2);
            sb += __shfl_xor_sync(0xffffffffu, sb, 1);
            sb += __shfl_xor_sync(0xffffffffu, sb, 2);
            if (tig == 0){
                psum[ra*8 + w] = sa;
                psum[rb*8 + w] = sb;
            }
        }

        CP_WAIT(0);          // V ready
        __syncthreads();     // [B3] Pb/psum complete, V visible

        // ---- stats update (one thread per row)
        if (tid < 64){
            int r = tid;
            float4 p0 = *(const float4*)&pmax[r*8];
            float4 p1 = *(const float4*)&pmax[r*8 + 4];
            float mx = fmaxf(fmaxf(fmaxf(p0.x, p0.y), fmaxf(p0.z, p0.w)),
                             fmaxf(fmaxf(p1.x, p1.y), fmaxf(p1.z, p1.w)));
            float mold = mrow[r];
            float mn = fmaxf(mx, mold);
            float al = __expf(mold - mn);
            float4 s0 = *(const float4*)&psum[r*8];
            float4 s1 = *(const float4*)&psum[r*8 + 4];
            float sum = s0.x + s0.y + s0.z + s0.w + s1.x + s1.y + s1.z + s1.w;
            lrow[r] = lrow[r]*al + sum;
            mrow[r] = mn;
        }

        // ---- rescale accumulators (vote-skip)
        {
            bool mine = true;
            #pragma unroll
            for (int mt = 0; mt < 4; mt++)
                mine = mine && (alA[mt] == 1.0f) && (alB[mt] == 1.0f);
            if (!__all_sync(0xffffffffu, mine)){
                #pragma unroll
                for (int mt = 0; mt < 4; mt++)
                    #pragma unroll
                    for (int nt = 0; nt < 2; nt++){
                        c[mt][nt][0] *= alA[mt];
                        c[mt][nt][1] *= alA[mt];
                        c[mt][nt][2] *= alB[mt];
                        c[mt][nt][3] *= alB[mt];
                    }
            }
        }

        // ---- PV: bf16 mma, 4 k-steps x 4 m x 2 n (warp e-slice = 16)
        #pragma unroll
        for (int ks = 0; ks < 4; ks++){
            uint32_t a[4][4];
            #pragma unroll
            for (int mt = 0; mt < 4; mt++){
                int r0 = (16*mt + gid)*36 + ks*8 + tig;
                int r1 = r0 + 8*36;
                a[mt][0] = Pbu[r0];
                a[mt][1] = Pbu[r1];
                a[mt][2] = Pbu[r0 + 4];
                a[mt][3] = Pbu[r1 + 4];
            }
            #pragma unroll
            for (int nt = 0; nt < 2; nt++){
                int eb = (16*w + 8*nt + gid)*36 + ks*8 + tig;
                uint32_t b0 = Vu[eb];
                uint32_t b1 = Vu[eb + 4];
                #pragma unroll
                for (int mt = 0; mt < 4; mt++)
                    mma_bf16(c[mt][nt], a[mt], b0, b1);
            }
        }
        __syncthreads();     // [B4] smem free for next tile
    }

    // epilogue: O/l -> g_O[b][n][e]
    float* Ob = Og + (size_t)b*NSP*CH;
    int e_base = eh*128 + 16*w;
    #pragma unroll
    for (int mt = 0; mt < 4; mt++){
        int qa = i0 + 16*mt + gid;
        float la = 1.0f / lrow[16*mt + gid];
        float lb = 1.0f / lrow[16*mt + gid + 8];
        #pragma unroll
        for (int nt = 0; nt < 2; nt++){
            int e = e_base + 8*nt + 2*tig;
            *(float2*)&Ob[(size_t)qa*CH + e] =
                make_float2(c[mt][nt][0]*la, c[mt][nt][1]*la);
            *(float2*)&Ob[(size_t)(qa + 8)*CH + e] =
                make_float2(c[mt][nt][2]*lb, c[mt][nt][3]*lb);
        }
    }
}

// ---------------- epilogue: out[b][e][n] = x + (gamma/sigma_v) * O^T --------
__global__ void epilogue_kernel(const float* __restrict__ x,
                                const float* __restrict__ gamma,
                                float* __restrict__ out){
    __shared__ float t[32][33];
    int b = blockIdx.z;
    int n0 = blockIdx.x * 32, e0 = blockIdx.y * 32;
    int tx = threadIdx.x, ty = threadIdx.y;   // 32 x 8
    float s = gamma[0] / g_sigma[2];
    const float* Ob = g_O + (size_t)b*NSP*CH;
    #pragma unroll
    for (int i = 0; i < 4; i++)
        t[ty + 8*i][tx] = Ob[(size_t)(n0 + ty + 8*i)*CH + e0 + tx];
    __syncthreads();
    #pragma unroll
    for (int i = 0; i < 4; i++){
        int e = e0 + ty + 8*i;
        size_t idx = (size_t)b*CH*NSP + (size_t)e*NSP + n0 + tx;
        out[idx] = x[idx] + s * t[tx][ty + 8*i];
    }
}

// ---------------- launch ----------------------------------------------------
extern "C" void kernel_launch(void* const* d_in, const int* in_sizes, int n_in,
                              void* d_out, int out_size){
    (void)in_sizes; (void)n_in; (void)out_size;
    const float* x     = (const float*)d_in[0];
    const float* wq    = (const float*)d_in[1];
    const float* wk    = (const float*)d_in[2];
    const float* wv    = (const float*)d_in[3];
    const float* gamma = (const float*)d_in[4];
    float* out = (float*)d_out;

    cudaFuncSetAttribute(flash_kernel,
                         cudaFuncAttributeMaxDynamicSharedMemorySize, FLASH_SMEM);

    float* Og;
    cudaGetSymbolAddress((void**)&Og, g_O);

    // ours #1..#3, flash = ours #4 (ncu profiles it with harness offset)
    init_kernel<<<1, 32>>>();
    sigma_qk_kernel<<<2, 1024>>>(wq, wk);
    proj_all_kernel<<<dim3(NSP/64, BATCH, 6), 256>>>(x, wq, wk, wv);
    flash_kernel<<<dim3(NSP/64, 2, BATCH), 256, FLASH_SMEM>>>(Og);

    // sigma_v chain (independent of flash): 5 squarings -> G^32 in g_GB
    gram_v_kernel<<<dim3(8, 8), 1024>>>(wv);
    sq_v_kernel<<<dim3(8, 8), 1024>>>(0, 1, 0);
    sq_v_kernel<<<dim3(8, 8), 1024>>>(1, 2, 1);
    sq_v_kernel<<<dim3(8, 8), 1024>>>(2, 1, 2);
    sq_v_kernel<<<dim3(8, 8), 1024>>>(1, 2, 3);
    sq_v_kernel<<<dim3(8, 8), 1024>>>(2, 1, 4);
    power_v_kernel<<<1, 1024>>>();

    epilogue_kernel<<<dim3(NSP/32, CH/32, BATCH), dim3(32, 8)>>>(x, gamma, out);
}